// round 1
// baseline (speedup 1.0000x reference)
#include <cuda_runtime.h>
#include <limits.h>

#define N_NODES 100000
#define MAX_E   1600000
#define TPB     256

// ---------------- scratch (device globals; alloc-free) ----------------
__device__ float g_q[N_NODES * 32];
__device__ float g_k[N_NODES * 32];
__device__ float g_v[N_NODES * 32];
__device__ float g_s[N_NODES * 32];
__device__ float g_alpha[MAX_E];
__device__ int   g_maxi[N_NODES];
__device__ float g_sum[N_NODES];
__device__ float g_agg[N_NODES * 32];
__device__ float g_h[N_NODES * 32];    // layer-1 output (32)
__device__ float g_h2[N_NODES * 16];   // layer-2 output (16)

// ordered-int encoding for float atomicMax (monotone, involutive)
__device__ __forceinline__ int f2o(float f) {
    int i = __float_as_int(f);
    return i ^ ((i >> 31) & 0x7fffffff);
}
__device__ __forceinline__ float o2f(int o) {
    return __int_as_float(o ^ ((o >> 31) & 0x7fffffff));
}

// ---------------- init segment state ----------------
__global__ void init_seg() {
    int i = blockIdx.x * blockDim.x + threadIdx.x;
    if (i < N_NODES) {
        g_sum[i]  = 0.f;
        g_maxi[i] = INT_MIN;
    }
    if (i < N_NODES * 32) g_agg[i] = 0.f;
}

// ---------------- node transform: q,k,v,s = x@W + b ----------------
// 32 lanes per node. LAYER==0 reads xin (emb); LAYER==1 reads g_h.
template <int DIN, int DOUT, int LAYER>
__global__ void node_xform(const float* __restrict__ xin,
                           const float* __restrict__ Wq, const float* __restrict__ bq,
                           const float* __restrict__ Wk, const float* __restrict__ bk,
                           const float* __restrict__ Wv, const float* __restrict__ bv,
                           const float* __restrict__ Ws, const float* __restrict__ bs) {
    __shared__ float sWq[DIN * DOUT], sWk[DIN * DOUT], sWv[DIN * DOUT], sWs[DIN * DOUT];
    __shared__ float sB[4 * DOUT];
    for (int i = threadIdx.x; i < DIN * DOUT; i += blockDim.x) {
        sWq[i] = Wq[i]; sWk[i] = Wk[i]; sWv[i] = Wv[i]; sWs[i] = Ws[i];
    }
    for (int i = threadIdx.x; i < DOUT; i += blockDim.x) {
        sB[i] = bq[i]; sB[DOUT + i] = bk[i]; sB[2 * DOUT + i] = bv[i]; sB[3 * DOUT + i] = bs[i];
    }
    __syncthreads();

    const float* __restrict__ x = (LAYER == 0) ? xin : g_h;

    int lane = threadIdx.x & 31;
    int node = (blockIdx.x * blockDim.x + threadIdx.x) >> 5;
    if (node >= N_NODES) return;

    float xv = x[node * DIN + lane];  // DIN == 32 always here
    int col = lane;
    float aq = 0.f, ak = 0.f, av = 0.f, as_ = 0.f;
#pragma unroll
    for (int kk = 0; kk < DIN; kk++) {
        float xk = __shfl_sync(0xffffffffu, xv, kk);
        if (col < DOUT) {
            aq  += xk * sWq[kk * DOUT + col];
            ak  += xk * sWk[kk * DOUT + col];
            av  += xk * sWv[kk * DOUT + col];
            as_ += xk * sWs[kk * DOUT + col];
        }
    }
    if (col < DOUT) {
        g_q[node * DOUT + col] = aq  + sB[col];
        g_k[node * DOUT + col] = ak  + sB[DOUT + col];
        g_v[node * DOUT + col] = av  + sB[2 * DOUT + col];
        g_s[node * DOUT + col] = as_ + sB[3 * DOUT + col];
    }
}

// ---------------- edge pass 1: alpha + segment max ----------------
// D/4 lanes per edge, float4 dot, intra-group shfl reduce.
template <int D>
__global__ void edge_alpha(const int* __restrict__ ei, int E, float rscale) {
    constexpr int G  = D / 4;
    constexpr int LG = (G == 8) ? 3 : 2;
    int t = blockIdx.x * blockDim.x + threadIdx.x;
    int e = t >> LG;
    int l = t & (G - 1);
    if (e >= E) return;
    int s = ei[e];
    int d = ei[E + e];

    float4 qv = *reinterpret_cast<const float4*>(g_q + d * D + l * 4);
    float4 kv = *reinterpret_cast<const float4*>(g_k + s * D + l * 4);
    float p = qv.x * kv.x + qv.y * kv.y + qv.z * kv.z + qv.w * kv.w;
#pragma unroll
    for (int off = 1; off < G; off <<= 1)
        p += __shfl_xor_sync(0xffffffffu, p, off);

    if (l == 0) {
        p *= rscale;
        g_alpha[e] = p;
        atomicMax(&g_maxi[d], f2o(p));
    }
}

// ---------------- edge pass 2: exp + scatter-add (unnormalized) ----------------
template <int D>
__global__ void edge_scatter(const int* __restrict__ ei, int E) {
    constexpr int G  = D / 4;
    constexpr int LG = (G == 8) ? 3 : 2;
    int t = blockIdx.x * blockDim.x + threadIdx.x;
    int e = t >> LG;
    int l = t & (G - 1);
    if (e >= E) return;
    int s = ei[e];
    int d = ei[E + e];

    float m = o2f(g_maxi[d]);
    float w = __expf(g_alpha[e] - m);
    if (l == 0) atomicAdd(&g_sum[d], w);

    float4 vv = *reinterpret_cast<const float4*>(g_v + s * D + l * 4);
    float4 r;
    r.x = w * vv.x; r.y = w * vv.y; r.z = w * vv.z; r.w = w * vv.w;
    atomicAdd(reinterpret_cast<float4*>(g_agg + d * D + l * 4), r);
}

// ---------------- node finish: h = relu(agg/(sum+eps) + s) ----------------
template <int D, int LAYER>
__global__ void node_finish() {
    int i = blockIdx.x * blockDim.x + threadIdx.x;
    if (i >= N_NODES * D) return;
    int n = i / D;
    float val = g_agg[i] / (g_sum[n] + 1e-16f) + g_s[i];
    val = val > 0.f ? val : 0.f;
    if (LAYER == 0) g_h[i] = val;
    else            g_h2[i] = val;
}

// ---------------- output: out = h2 @ Wo + bo ----------------
__global__ void out_kernel(const float* __restrict__ Wo, const float* __restrict__ bo,
                           float* __restrict__ out) {
    int n = blockIdx.x * blockDim.x + threadIdx.x;
    if (n >= N_NODES) return;
    float a0 = bo[0], a1 = bo[1];
#pragma unroll
    for (int kk = 0; kk < 16; kk++) {
        float x = g_h2[n * 16 + kk];
        a0 += x * Wo[kk * 2 + 0];
        a1 += x * Wo[kk * 2 + 1];
    }
    out[n * 2 + 0] = a0;
    out[n * 2 + 1] = a1;
}

extern "C" void kernel_launch(void* const* d_in, const int* in_sizes, int n_in,
                              void* d_out, int out_size) {
    const int*   ei  = (const int*)  d_in[0];
    const float* emb = (const float*)d_in[1];
    const float* Wq1 = (const float*)d_in[2];  const float* bq1 = (const float*)d_in[3];
    const float* Wk1 = (const float*)d_in[4];  const float* bk1 = (const float*)d_in[5];
    const float* Wv1 = (const float*)d_in[6];  const float* bv1 = (const float*)d_in[7];
    const float* Ws1 = (const float*)d_in[8];  const float* bs1 = (const float*)d_in[9];
    const float* Wq2 = (const float*)d_in[10]; const float* bq2 = (const float*)d_in[11];
    const float* Wk2 = (const float*)d_in[12]; const float* bk2 = (const float*)d_in[13];
    const float* Wv2 = (const float*)d_in[14]; const float* bv2 = (const float*)d_in[15];
    const float* Ws2 = (const float*)d_in[16]; const float* bs2 = (const float*)d_in[17];
    const float* Wo  = (const float*)d_in[18]; const float* bo  = (const float*)d_in[19];
    float* out = (float*)d_out;

    int E = in_sizes[0] / 2;

    int nodeBlocks  = (N_NODES * 32 + TPB - 1) / TPB;   // 32 lanes/node
    int elemBlocks  = (N_NODES * 32 + TPB - 1) / TPB;
    int elemBlocks16 = (N_NODES * 16 + TPB - 1) / TPB;
    int eBlocks8 = (E * 8 + TPB - 1) / TPB;
    int eBlocks4 = (E * 4 + TPB - 1) / TPB;

    // ---- layer 1 (D=32) ----
    init_seg<<<elemBlocks, TPB>>>();
    node_xform<32, 32, 0><<<nodeBlocks, TPB>>>(emb, Wq1, bq1, Wk1, bk1, Wv1, bv1, Ws1, bs1);
    edge_alpha<32><<<eBlocks8, TPB>>>(ei, E, 0.17677669529663687f /* 1/sqrt(32) */);
    edge_scatter<32><<<eBlocks8, TPB>>>(ei, E);
    node_finish<32, 0><<<elemBlocks, TPB>>>();

    // ---- layer 2 (D=16) ----
    init_seg<<<elemBlocks, TPB>>>();
    node_xform<32, 16, 1><<<nodeBlocks, TPB>>>(emb /*unused*/, Wq2, bq2, Wk2, bk2, Wv2, bv2, Ws2, bs2);
    edge_alpha<16><<<eBlocks4, TPB>>>(ei, E, 0.25f /* 1/sqrt(16) */);
    edge_scatter<16><<<eBlocks4, TPB>>>(ei, E);
    node_finish<16, 1><<<elemBlocks16, TPB>>>();

    // ---- output head ----
    out_kernel<<<(N_NODES + TPB - 1) / TPB, TPB>>>(Wo, bo, out);
}

// round 3
// speedup vs baseline: 1.2453x; 1.2453x over previous
#include <cuda_runtime.h>
#include <limits.h>

#define N_NODES 100000
#define TPB     256
#define EPS     1e-16f

// ---------------- scratch (device globals; alloc-free) ----------------
__device__ float g_q[N_NODES * 32];
__device__ float g_k[N_NODES * 32];
__device__ float g_v[N_NODES * 32];
__device__ float g_s[N_NODES * 32];
__device__ float g_sum[N_NODES];
__device__ float g_agg[N_NODES * 32];

// ---------------- layer-1 transform + zero segment state ----------------
// 32 lanes per node: q,k,v,s = emb@W + b ; agg=0 ; sum=0
__global__ void xform1(const float* __restrict__ x,
                       const float* __restrict__ Wq, const float* __restrict__ bq,
                       const float* __restrict__ Wk, const float* __restrict__ bk,
                       const float* __restrict__ Wv, const float* __restrict__ bv,
                       const float* __restrict__ Ws, const float* __restrict__ bs) {
    __shared__ float sWq[32 * 32], sWk[32 * 32], sWv[32 * 32], sWs[32 * 32];
    __shared__ float sB[4 * 32];
    for (int i = threadIdx.x; i < 32 * 32; i += blockDim.x) {
        sWq[i] = Wq[i]; sWk[i] = Wk[i]; sWv[i] = Wv[i]; sWs[i] = Ws[i];
    }
    for (int i = threadIdx.x; i < 32; i += blockDim.x) {
        sB[i] = bq[i]; sB[32 + i] = bk[i]; sB[64 + i] = bv[i]; sB[96 + i] = bs[i];
    }
    __syncthreads();

    int lane = threadIdx.x & 31;
    int node = (blockIdx.x * blockDim.x + threadIdx.x) >> 5;
    if (node >= N_NODES) return;

    float xv = x[node * 32 + lane];
    float aq = 0.f, ak = 0.f, av = 0.f, as_ = 0.f;
#pragma unroll
    for (int kk = 0; kk < 32; kk++) {
        float xk = __shfl_sync(0xffffffffu, xv, kk);
        aq  += xk * sWq[kk * 32 + lane];
        ak  += xk * sWk[kk * 32 + lane];
        av  += xk * sWv[kk * 32 + lane];
        as_ += xk * sWs[kk * 32 + lane];
    }
    int o = node * 32 + lane;
    g_q[o] = aq  + sB[lane];
    g_k[o] = ak  + sB[32 + lane];
    g_v[o] = av  + sB[64 + lane];
    g_s[o] = as_ + sB[96 + lane];
    g_agg[o] = 0.f;
    if (lane == 0) g_sum[node] = 0.f;
}

// ---------------- fused edge pass (no max pass; softmax shift-invariant) ----
// D/4 lanes per edge: alpha = (q[d].k[s])*rscale ; w = exp(alpha)
// atomicAdd sum[d] += w ; agg[d] += w*v[s]
template <int D>
__global__ void edge_fused(const int* __restrict__ ei, int E, float rscale) {
    constexpr int G  = D / 4;
    constexpr int LG = (G == 8) ? 3 : 2;
    int t = blockIdx.x * blockDim.x + threadIdx.x;
    int e = t >> LG;
    int l = t & (G - 1);
    if (e >= E) return;
    int s = __ldg(ei + e);
    int d = __ldg(ei + E + e);

    const float4 qv = *reinterpret_cast<const float4*>(g_q + d * D + l * 4);
    const float4 kv = *reinterpret_cast<const float4*>(g_k + s * D + l * 4);
    float p = qv.x * kv.x + qv.y * kv.y + qv.z * kv.z + qv.w * kv.w;
#pragma unroll
    for (int off = 1; off < G; off <<= 1)
        p += __shfl_xor_sync(0xffffffffu, p, off);

    float w = __expf(fminf(p * rscale, 85.0f));  // clamp: overflow insurance only
    if (l == 0) atomicAdd(&g_sum[d], w);

    const float4 vv = *reinterpret_cast<const float4*>(g_v + s * D + l * 4);
    float4 r;
    r.x = w * vv.x; r.y = w * vv.y; r.z = w * vv.z; r.w = w * vv.w;
    atomicAdd(reinterpret_cast<float4*>(g_agg + d * D + l * 4), r);
}

// ---------------- finish layer 1 + layer-2 transform + re-zero ------------
// 32 lanes per node: h = relu(agg/(sum+eps)+s); q2..s2 = h@W2+b2 (16 cols);
// agg/sum re-zeroed for layer 2.
__global__ void finish1_xform2(const float* __restrict__ Wq, const float* __restrict__ bq,
                               const float* __restrict__ Wk, const float* __restrict__ bk,
                               const float* __restrict__ Wv, const float* __restrict__ bv,
                               const float* __restrict__ Ws, const float* __restrict__ bs) {
    __shared__ float sWq[32 * 16], sWk[32 * 16], sWv[32 * 16], sWs[32 * 16];
    __shared__ float sB[4 * 16];
    for (int i = threadIdx.x; i < 32 * 16; i += blockDim.x) {
        sWq[i] = Wq[i]; sWk[i] = Wk[i]; sWv[i] = Wv[i]; sWs[i] = Ws[i];
    }
    for (int i = threadIdx.x; i < 16; i += blockDim.x) {
        sB[i] = bq[i]; sB[16 + i] = bk[i]; sB[32 + i] = bv[i]; sB[48 + i] = bs[i];
    }
    __syncthreads();

    int lane = threadIdx.x & 31;
    int node = (blockIdx.x * blockDim.x + threadIdx.x) >> 5;
    if (node >= N_NODES) return;

    int o32 = node * 32 + lane;
    float rs = 1.0f / (g_sum[node] + EPS);
    float h  = g_agg[o32] * rs + g_s[o32];
    h = h > 0.f ? h : 0.f;

    // re-zero for layer 2 (safe: each element touched only by this thread/warp)
    g_agg[o32] = 0.f;
    if (lane == 0) g_sum[node] = 0.f;

    float aq = 0.f, ak = 0.f, av = 0.f, as_ = 0.f;
#pragma unroll
    for (int kk = 0; kk < 32; kk++) {
        float xk = __shfl_sync(0xffffffffu, h, kk);
        if (lane < 16) {
            aq  += xk * sWq[kk * 16 + lane];
            ak  += xk * sWk[kk * 16 + lane];
            av  += xk * sWv[kk * 16 + lane];
            as_ += xk * sWs[kk * 16 + lane];
        }
    }
    if (lane < 16) {
        int o = node * 16 + lane;
        g_q[o] = aq  + sB[lane];
        g_k[o] = ak  + sB[16 + lane];
        g_v[o] = av  + sB[32 + lane];
        g_s[o] = as_ + sB[48 + lane];
    }
}

// ---------------- finish layer 2 + output head -----------------------------
// 16 lanes per node: h2 = relu(agg/(sum+eps)+s); out = h2@Wo + bo
__global__ void finish2_out(const float* __restrict__ Wo, const float* __restrict__ bo,
                            float* __restrict__ out) {
    int t = blockIdx.x * blockDim.x + threadIdx.x;
    int node = t >> 4;
    int l = t & 15;
    if (node >= N_NODES) return;

    int o = node * 16 + l;
    float rs = 1.0f / (g_sum[node] + EPS);
    float h = g_agg[o] * rs + g_s[o];
    h = h > 0.f ? h : 0.f;

    float p0 = h * __ldg(Wo + l * 2 + 0);
    float p1 = h * __ldg(Wo + l * 2 + 1);
#pragma unroll
    for (int off = 1; off < 16; off <<= 1) {
        p0 += __shfl_xor_sync(0xffffffffu, p0, off);
        p1 += __shfl_xor_sync(0xffffffffu, p1, off);
    }
    if (l == 0) {
        out[node * 2 + 0] = p0 + __ldg(bo + 0);
        out[node * 2 + 1] = p1 + __ldg(bo + 1);
    }
}

extern "C" void kernel_launch(void* const* d_in, const int* in_sizes, int n_in,
                              void* d_out, int out_size) {
    const int*   ei  = (const int*)  d_in[0];
    const float* emb = (const float*)d_in[1];
    const float* Wq1 = (const float*)d_in[2];  const float* bq1 = (const float*)d_in[3];
    const float* Wk1 = (const float*)d_in[4];  const float* bk1 = (const float*)d_in[5];
    const float* Wv1 = (const float*)d_in[6];  const float* bv1 = (const float*)d_in[7];
    const float* Ws1 = (const float*)d_in[8];  const float* bs1 = (const float*)d_in[9];
    const float* Wq2 = (const float*)d_in[10]; const float* bq2 = (const float*)d_in[11];
    const float* Wk2 = (const float*)d_in[12]; const float* bk2 = (const float*)d_in[13];
    const float* Wv2 = (const float*)d_in[14]; const float* bv2 = (const float*)d_in[15];
    const float* Ws2 = (const float*)d_in[16]; const float* bs2 = (const float*)d_in[17];
    const float* Wo  = (const float*)d_in[18]; const float* bo  = (const float*)d_in[19];
    float* out = (float*)d_out;

    int E = in_sizes[0] / 2;

    int nodeBlocks = (N_NODES * 32 + TPB - 1) / TPB;
    int eBlocks8 = (E * 8 + TPB - 1) / TPB;
    int eBlocks4 = (E * 4 + TPB - 1) / TPB;

    // layer 1
    xform1<<<nodeBlocks, TPB>>>(emb, Wq1, bq1, Wk1, bk1, Wv1, bv1, Ws1, bs1);
    edge_fused<32><<<eBlocks8, TPB>>>(ei, E, 0.17677669529663687f);  // 1/sqrt(32)

    // layer 2
    finish1_xform2<<<nodeBlocks, TPB>>>(Wq2, bq2, Wk2, bk2, Wv2, bv2, Ws2, bs2);
    edge_fused<16><<<eBlocks4, TPB>>>(ei, E, 0.25f);                 // 1/sqrt(16)

    // output head
    finish2_out<<<(N_NODES * 16 + TPB - 1) / TPB, TPB>>>(Wo, bo, out);
}